// round 1
// baseline (speedup 1.0000x reference)
#include <cuda_runtime.h>

#define BSZ 512
#define IN_DIM 128
#define H2 512
#define OUT_DIM 25

// Scratch (static device globals — no allocation)
__device__ float g_h[BSZ * H2];
__device__ float g_Q[BSZ * H2];
__device__ float g_K[BSZ * H2];
__device__ float g_V[BSZ * H2];
__device__ float g_ctx[BSZ * H2];

__device__ __forceinline__ float ex2f(float x) {
    float y;
    asm("ex2.approx.ftz.f32 %0, %1;" : "=f"(y) : "f"(x));
    return y;
}

__device__ __forceinline__ float siluf(float x) {
    // x * sigmoid(x) = x / (1 + exp(-x)) ; exp(-x) = 2^(-x*log2e)
    float e = ex2f(-1.44269504f * x);
    return __fdividef(x, 1.0f + e);
}

// ---------------------------------------------------------------------------
// C[M,N] = silu(A[M,Kd] @ W[N,Kd]^T + bias[N])
// 64x64 tile, 16x16 threads, 4x4 per thread, k-tile 16, k-major smem.
// z-dim selects among 3 (W, bias, C) triples for the fused Q/K/V launch.
// ---------------------------------------------------------------------------
__global__ void gemm_silu_kernel(
    const float* __restrict__ A,
    const float* __restrict__ W0, const float* __restrict__ W1, const float* __restrict__ W2,
    const float* __restrict__ bias0, const float* __restrict__ bias1, const float* __restrict__ bias2,
    float* __restrict__ C0, float* __restrict__ C1, float* __restrict__ C2,
    int M, int N, int Kd)
{
    const float* W    = (blockIdx.z == 0) ? W0    : (blockIdx.z == 1) ? W1    : W2;
    const float* bias = (blockIdx.z == 0) ? bias0 : (blockIdx.z == 1) ? bias1 : bias2;
    float*       C    = (blockIdx.z == 0) ? C0    : (blockIdx.z == 1) ? C1    : C2;

    __shared__ float As[16][68];  // [k][row], stride 68 keeps float4 align + no bank conflicts
    __shared__ float Ws[16][68];  // [k][col]

    const int tx = threadIdx.x;        // 0..15
    const int ty = threadIdx.y;        // 0..15
    const int tid = ty * 16 + tx;      // 0..255
    const int row0 = blockIdx.y * 64;
    const int col0 = blockIdx.x * 64;

    const int lr = tid >> 2;           // 0..63  (tile row/col to load)
    const int lc = (tid & 3) * 4;      // 0,4,8,12 (k offset to load)

    float acc[4][4];
#pragma unroll
    for (int i = 0; i < 4; i++)
#pragma unroll
        for (int j = 0; j < 4; j++) acc[i][j] = 0.0f;

    for (int k0 = 0; k0 < Kd; k0 += 16) {
        float4 av = *(const float4*)&A[(row0 + lr) * Kd + k0 + lc];
        float4 wv = *(const float4*)&W[(col0 + lr) * Kd + k0 + lc];
        As[lc + 0][lr] = av.x; As[lc + 1][lr] = av.y;
        As[lc + 2][lr] = av.z; As[lc + 3][lr] = av.w;
        Ws[lc + 0][lr] = wv.x; Ws[lc + 1][lr] = wv.y;
        Ws[lc + 2][lr] = wv.z; Ws[lc + 3][lr] = wv.w;
        __syncthreads();

#pragma unroll
        for (int kk = 0; kk < 16; kk++) {
            float4 a4 = *(const float4*)&As[kk][ty * 4];
            float4 w4 = *(const float4*)&Ws[kk][tx * 4];
            float av_[4] = {a4.x, a4.y, a4.z, a4.w};
            float wv_[4] = {w4.x, w4.y, w4.z, w4.w};
#pragma unroll
            for (int i = 0; i < 4; i++)
#pragma unroll
                for (int j = 0; j < 4; j++)
                    acc[i][j] = fmaf(av_[i], wv_[j], acc[i][j]);
        }
        __syncthreads();
    }

#pragma unroll
    for (int i = 0; i < 4; i++) {
        int r = row0 + ty * 4 + i;
        float4 o;
        o.x = siluf(acc[i][0] + bias[col0 + tx * 4 + 0]);
        o.y = siluf(acc[i][1] + bias[col0 + tx * 4 + 1]);
        o.z = siluf(acc[i][2] + bias[col0 + tx * 4 + 2]);
        o.w = siluf(acc[i][3] + bias[col0 + tx * 4 + 3]);
        *(float4*)&C[r * N + col0 + tx * 4] = o;
    }
}

// ---------------------------------------------------------------------------
// Attention: scores[b,i,j] = Q[b,i]*K[b,j]; softmax over j; ctx = silu(attn@V).
// Rank-1 structure => row max is q*Kmax (q>=0) or q*Kmin (q<0).
// One block per batch row, 512 threads (thread i owns output i).
// K pre-scaled by log2e so inner loop is FFMA + EX2 + FADD + FFMA.
// ---------------------------------------------------------------------------
__global__ void attn_kernel() {
    __shared__ float Ks[H2];
    __shared__ float Vs[H2];
    __shared__ float redmax[16];
    __shared__ float redmin[16];
    __shared__ float s_kmax, s_kmin;

    const int b = blockIdx.x;
    const int t = threadIdx.x;

    float k = g_K[b * H2 + t] * 1.44269504f;  // K * log2(e)
    Ks[t] = k;
    Vs[t] = g_V[b * H2 + t];

    float kmx = k, kmn = k;
#pragma unroll
    for (int o = 16; o; o >>= 1) {
        kmx = fmaxf(kmx, __shfl_xor_sync(0xFFFFFFFFu, kmx, o));
        kmn = fminf(kmn, __shfl_xor_sync(0xFFFFFFFFu, kmn, o));
    }
    if ((t & 31) == 0) { redmax[t >> 5] = kmx; redmin[t >> 5] = kmn; }
    __syncthreads();
    if (t == 0) {
        float a = redmax[0], bm = redmin[0];
#pragma unroll
        for (int i = 1; i < 16; i++) {
            a  = fmaxf(a,  redmax[i]);
            bm = fminf(bm, redmin[i]);
        }
        s_kmax = a; s_kmin = bm;
    }
    __syncthreads();

    const float q = g_Q[b * H2 + t];
    const float kext = (q >= 0.0f) ? s_kmax : s_kmin;
    const float c = -q * kext;  // guarantees exponent arg <= 0

    float sE = 0.0f, sEV = 0.0f;
#pragma unroll 8
    for (int j = 0; j < H2; j++) {
        float e = ex2f(fmaf(q, Ks[j], c));
        sE += e;
        sEV = fmaf(e, Vs[j], sEV);
    }
    g_ctx[b * H2 + t] = siluf(__fdividef(sEV, sE));
}

// ---------------------------------------------------------------------------
// y = silu(ctx @ W_out^T + b_out) [B,25]; then quadratic-form epilogue.
// One block per batch, 256 threads; warp w handles outputs n = w + 8r.
// ---------------------------------------------------------------------------
__global__ void out_kernel(const float* __restrict__ W_out,
                           const float* __restrict__ b_out,
                           float* __restrict__ out)
{
    __shared__ float cs[H2];
    __shared__ float ys[32];

    const int b = blockIdx.x;
    const int t = threadIdx.x;  // 0..255

    cs[t]       = g_ctx[b * H2 + t];
    cs[t + 256] = g_ctx[b * H2 + t + 256];
    __syncthreads();

    const int w = t >> 5, lane = t & 31;
#pragma unroll
    for (int r = 0; r < 4; r++) {
        int n = w + 8 * r;
        if (n < OUT_DIM) {
            float s = 0.0f;
#pragma unroll
            for (int kk = 0; kk < 16; kk++)
                s = fmaf(cs[lane + 32 * kk], W_out[n * H2 + lane + 32 * kk], s);
#pragma unroll
            for (int o = 16; o; o >>= 1)
                s += __shfl_xor_sync(0xFFFFFFFFu, s, o);
            if (lane == 0) ys[n] = siluf(s + b_out[n]);
        }
    }
    __syncthreads();

    if (t == 0) {
        float g[5];
#pragma unroll
        for (int gi = 0; gi < 5; gi++) {
            float s = 0.0f;
#pragma unroll
            for (int i = 0; i < 5; i++) {
                float yv = ys[gi * 5 + i];
                s = fmaf(yv, yv, s);
            }
            g[gi] = s;
        }
        // M = [[m11,0,m12,0],[0,m11,0,m12],[m21,0,m22,0],[0,m21,0,m22]]
        // quad = m11(q0^2+q1^2) + (m12+m21)(q0q2+q1q3) + m22(q2^2+q3^2)
        const float m11 = g[0], m12 = g[1], m21 = g[2], m22 = g[3], mpp = g[4];
        const float q0 = ys[0], q1 = ys[1], q2 = ys[2], q3 = ys[3];
        float quad = m11 * (q0 * q0 + q1 * q1)
                   + (m12 + m21) * (q0 * q2 + q1 * q3)
                   + m22 * (q2 * q2 + q3 * q3);
        out[b] = quad + mpp;
    }
}

// ---------------------------------------------------------------------------
extern "C" void kernel_launch(void* const* d_in, const int* in_sizes, int n_in,
                              void* d_out, int out_size)
{
    const float* x     = (const float*)d_in[0];
    // d_in[1] = na (int32, always 4; q = y[:, :4] is hardcoded) — unused
    const float* W_in  = (const float*)d_in[2];
    const float* b_in  = (const float*)d_in[3];
    const float* Aq    = (const float*)d_in[4];
    const float* Bq    = (const float*)d_in[5];
    const float* Ak    = (const float*)d_in[6];
    const float* Bk    = (const float*)d_in[7];
    const float* Av    = (const float*)d_in[8];
    const float* Bv    = (const float*)d_in[9];
    const float* W_out = (const float*)d_in[10];
    const float* b_out = (const float*)d_in[11];
    float* out = (float*)d_out;

    float *h, *Qp, *Kp, *Vp;
    cudaGetSymbolAddress((void**)&h,  g_h);
    cudaGetSymbolAddress((void**)&Qp, g_Q);
    cudaGetSymbolAddress((void**)&Kp, g_K);
    cudaGetSymbolAddress((void**)&Vp, g_V);

    dim3 blk(16, 16);

    // h = silu(x @ W_in^T + b_in)   [512,128] @ [128,512] -> [512,512]
    gemm_silu_kernel<<<dim3(H2 / 64, BSZ / 64, 1), blk>>>(
        x, W_in, W_in, W_in, b_in, b_in, b_in, h, h, h, BSZ, H2, IN_DIM);

    // Q,K,V = silu(h @ A*^T + B*) fused via grid.z
    gemm_silu_kernel<<<dim3(H2 / 64, BSZ / 64, 3), blk>>>(
        h, Aq, Ak, Av, Bq, Bk, Bv, Qp, Kp, Vp, BSZ, H2, H2);

    // rank-1 softmax attention -> ctx
    attn_kernel<<<BSZ, H2>>>();

    // output projection + quadratic-form epilogue
    out_kernel<<<BSZ, 256>>>(W_out, b_out, out);
}

// round 2
// speedup vs baseline: 1.0482x; 1.0482x over previous
#include <cuda_runtime.h>

#define BSZ 512
#define IN_DIM 128
#define H2 512
#define OUT_DIM 25

// Scratch (static device globals — no allocation)
__device__ float g_h[BSZ * H2];
__device__ float g_Q[BSZ * H2];
__device__ float g_K[BSZ * H2];
__device__ float g_V[BSZ * H2];

__device__ __forceinline__ float ex2f(float x) {
    float y;
    asm("ex2.approx.ftz.f32 %0, %1;" : "=f"(y) : "f"(x));
    return y;
}

__device__ __forceinline__ float siluf(float x) {
    float e = ex2f(-1.44269504f * x);
    return __fdividef(x, 1.0f + e);
}

// packed f32x2 helpers (Blackwell FFMA2 path)
__device__ __forceinline__ unsigned long long dup2(float x) {
    unsigned long long r;
    asm("mov.b64 %0, {%1, %1};" : "=l"(r) : "f"(x));
    return r;
}
__device__ __forceinline__ void ffma2(unsigned long long& d,
                                      unsigned long long a,
                                      unsigned long long b) {
    asm("fma.rn.f32x2 %0, %1, %2, %0;" : "+l"(d) : "l"(a), "l"(b));
}
__device__ __forceinline__ void unpack2(unsigned long long v, float& lo, float& hi) {
    asm("mov.b64 {%0, %1}, %2;" : "=f"(lo), "=f"(hi) : "l"(v));
}

// ---------------------------------------------------------------------------
// C[M,N] = silu(A[M,Kd] @ W[N,Kd]^T + bias[N])
// 64x64 block tile, 64 threads, 8x8 per thread via packed f32x2 accumulators.
// Double-buffered smem (kt=8), k-major layout, grid.z selects W/bias/C triple.
// ---------------------------------------------------------------------------
__global__ void __launch_bounds__(64) gemm_silu_kernel(
    const float* __restrict__ A,
    const float* __restrict__ W0, const float* __restrict__ W1, const float* __restrict__ W2,
    const float* __restrict__ bias0, const float* __restrict__ bias1, const float* __restrict__ bias2,
    float* __restrict__ C0, float* __restrict__ C1, float* __restrict__ C2,
    int N, int Kd)
{
    const float* W    = (blockIdx.z == 0) ? W0    : (blockIdx.z == 1) ? W1    : W2;
    const float* bias = (blockIdx.z == 0) ? bias0 : (blockIdx.z == 1) ? bias1 : bias2;
    float*       C    = (blockIdx.z == 0) ? C0    : (blockIdx.z == 1) ? C1    : C2;

    __shared__ float As[2][8][68];   // [buf][k][row]
    __shared__ float Ws[2][8][68];   // [buf][k][col]

    const int tid  = threadIdx.x;        // 0..63
    const int tx8  = (tid & 7) * 8;      // output col sub-tile
    const int ty8  = (tid >> 3) * 8;     // output row sub-tile
    const int row0 = blockIdx.y * 64;
    const int col0 = blockIdx.x * 64;

    // gmem load mapping: each thread fetches 2 float4 per operand per k-tile
    const int lrow = tid >> 1;           // 0..31 (+32 for second)
    const int lk   = (tid & 1) * 4;      // 0 or 4

    unsigned long long acc[4][8];
#pragma unroll
    for (int ip = 0; ip < 4; ip++)
#pragma unroll
        for (int j = 0; j < 8; j++) acc[ip][j] = 0ull;

    const int nk = Kd >> 3;
    float4 pa0, pa1, pw0, pw1;

    // prologue: load + store tile 0
    {
        const float* Ab = A + (row0 + lrow) * Kd + lk;
        const float* Wb = W + (col0 + lrow) * Kd + lk;
        pa0 = *(const float4*)(Ab);
        pa1 = *(const float4*)(Ab + 32 * Kd);
        pw0 = *(const float4*)(Wb);
        pw1 = *(const float4*)(Wb + 32 * Kd);
        As[0][lk + 0][lrow] = pa0.x; As[0][lk + 1][lrow] = pa0.y;
        As[0][lk + 2][lrow] = pa0.z; As[0][lk + 3][lrow] = pa0.w;
        As[0][lk + 0][lrow + 32] = pa1.x; As[0][lk + 1][lrow + 32] = pa1.y;
        As[0][lk + 2][lrow + 32] = pa1.z; As[0][lk + 3][lrow + 32] = pa1.w;
        Ws[0][lk + 0][lrow] = pw0.x; Ws[0][lk + 1][lrow] = pw0.y;
        Ws[0][lk + 2][lrow] = pw0.z; Ws[0][lk + 3][lrow] = pw0.w;
        Ws[0][lk + 0][lrow + 32] = pw1.x; Ws[0][lk + 1][lrow + 32] = pw1.y;
        Ws[0][lk + 2][lrow + 32] = pw1.z; Ws[0][lk + 3][lrow + 32] = pw1.w;
    }
    __syncthreads();

    for (int t = 0; t < nk; t++) {
        const int cur = t & 1;
        if (t + 1 < nk) {
            const int k0 = (t + 1) * 8;
            const float* Ab = A + (row0 + lrow) * Kd + k0 + lk;
            const float* Wb = W + (col0 + lrow) * Kd + k0 + lk;
            pa0 = *(const float4*)(Ab);
            pa1 = *(const float4*)(Ab + 32 * Kd);
            pw0 = *(const float4*)(Wb);
            pw1 = *(const float4*)(Wb + 32 * Kd);
        }

#pragma unroll
        for (int kk = 0; kk < 8; kk++) {
            const float* arow = &As[cur][kk][0];
            const float* wrow = &Ws[cur][kk][0];
            unsigned long long a2[4];
#pragma unroll
            for (int ip = 0; ip < 4; ip++)
                a2[ip] = *(const unsigned long long*)(arow + ty8 + 2 * ip);
            float4 w0 = *(const float4*)(wrow + tx8);
            float4 w1 = *(const float4*)(wrow + tx8 + 4);
            unsigned long long wd[8];
            wd[0] = dup2(w0.x); wd[1] = dup2(w0.y);
            wd[2] = dup2(w0.z); wd[3] = dup2(w0.w);
            wd[4] = dup2(w1.x); wd[5] = dup2(w1.y);
            wd[6] = dup2(w1.z); wd[7] = dup2(w1.w);
#pragma unroll
            for (int j = 0; j < 8; j++)
#pragma unroll
                for (int ip = 0; ip < 4; ip++)
                    ffma2(acc[ip][j], a2[ip], wd[j]);
        }

        if (t + 1 < nk) {
            const int nb = (t + 1) & 1;
            As[nb][lk + 0][lrow] = pa0.x; As[nb][lk + 1][lrow] = pa0.y;
            As[nb][lk + 2][lrow] = pa0.z; As[nb][lk + 3][lrow] = pa0.w;
            As[nb][lk + 0][lrow + 32] = pa1.x; As[nb][lk + 1][lrow + 32] = pa1.y;
            As[nb][lk + 2][lrow + 32] = pa1.z; As[nb][lk + 3][lrow + 32] = pa1.w;
            Ws[nb][lk + 0][lrow] = pw0.x; Ws[nb][lk + 1][lrow] = pw0.y;
            Ws[nb][lk + 2][lrow] = pw0.z; Ws[nb][lk + 3][lrow] = pw0.w;
            Ws[nb][lk + 0][lrow + 32] = pw1.x; Ws[nb][lk + 1][lrow + 32] = pw1.y;
            Ws[nb][lk + 2][lrow + 32] = pw1.z; Ws[nb][lk + 3][lrow + 32] = pw1.w;
            __syncthreads();
        }
    }

    // epilogue: unpack pairs (rows ty8+2ip, ty8+2ip+1), add bias, silu, store
    float b[8];
#pragma unroll
    for (int j = 0; j < 8; j++) b[j] = bias[col0 + tx8 + j];

#pragma unroll
    for (int ip = 0; ip < 4; ip++) {
        float r0[8], r1[8];
#pragma unroll
        for (int j = 0; j < 8; j++) unpack2(acc[ip][j], r0[j], r1[j]);
        float4 o;
        float* Crow0 = C + (row0 + ty8 + 2 * ip) * N + col0 + tx8;
        float* Crow1 = Crow0 + N;
        o.x = siluf(r0[0] + b[0]); o.y = siluf(r0[1] + b[1]);
        o.z = siluf(r0[2] + b[2]); o.w = siluf(r0[3] + b[3]);
        *(float4*)(Crow0) = o;
        o.x = siluf(r0[4] + b[4]); o.y = siluf(r0[5] + b[5]);
        o.z = siluf(r0[6] + b[6]); o.w = siluf(r0[7] + b[7]);
        *(float4*)(Crow0 + 4) = o;
        o.x = siluf(r1[0] + b[0]); o.y = siluf(r1[1] + b[1]);
        o.z = siluf(r1[2] + b[2]); o.w = siluf(r1[3] + b[3]);
        *(float4*)(Crow1) = o;
        o.x = siluf(r1[4] + b[4]); o.y = siluf(r1[5] + b[5]);
        o.z = siluf(r1[6] + b[6]); o.w = siluf(r1[7] + b[7]);
        *(float4*)(Crow1 + 4) = o;
    }
}

// ---------------------------------------------------------------------------
// Attention + output projection + quadratic epilogue, fused per batch row.
// scores rank-1 => row max is q*Kmax (q>=0) or q*Kmin (q<0).
// 512 threads: thread i owns ctx[i]; then 16 warps do the 25-way projection.
// ---------------------------------------------------------------------------
__global__ void attn_out_kernel(const float* __restrict__ W_out,
                                const float* __restrict__ b_out,
                                float* __restrict__ out)
{
    __shared__ float Ks[H2];
    __shared__ float Vs[H2];
    __shared__ float cs[H2];
    __shared__ float redmax[16];
    __shared__ float redmin[16];
    __shared__ float s_kmax, s_kmin;
    __shared__ float ys[32];

    const int b = blockIdx.x;
    const int t = threadIdx.x;

    float k = g_K[b * H2 + t] * 1.44269504f;  // K * log2(e)
    Ks[t] = k;
    Vs[t] = g_V[b * H2 + t];

    float kmx = k, kmn = k;
#pragma unroll
    for (int o = 16; o; o >>= 1) {
        kmx = fmaxf(kmx, __shfl_xor_sync(0xFFFFFFFFu, kmx, o));
        kmn = fminf(kmn, __shfl_xor_sync(0xFFFFFFFFu, kmn, o));
    }
    if ((t & 31) == 0) { redmax[t >> 5] = kmx; redmin[t >> 5] = kmn; }
    __syncthreads();
    if (t == 0) {
        float a = redmax[0], bm = redmin[0];
#pragma unroll
        for (int i = 1; i < 16; i++) {
            a  = fmaxf(a,  redmax[i]);
            bm = fminf(bm, redmin[i]);
        }
        s_kmax = a; s_kmin = bm;
    }
    __syncthreads();

    const float q = g_Q[b * H2 + t];
    const float kext = (q >= 0.0f) ? s_kmax : s_kmin;
    const float c = -q * kext;  // exponent arg <= 0 guaranteed

    float sE = 0.0f, sEV = 0.0f;
#pragma unroll 8
    for (int j = 0; j < H2; j++) {
        float e = ex2f(fmaf(q, Ks[j], c));
        sE += e;
        sEV = fmaf(e, Vs[j], sEV);
    }
    cs[t] = siluf(__fdividef(sEV, sE));
    __syncthreads();

    // output projection: warp w handles n = w and n = w + 16 (n < 25)
    const int w = t >> 5, lane = t & 31;
#pragma unroll
    for (int r = 0; r < 2; r++) {
        int n = w + 16 * r;
        if (n < OUT_DIM) {
            const float* Wr = W_out + n * H2;
            float s = 0.0f;
#pragma unroll
            for (int kk = 0; kk < 16; kk++)
                s = fmaf(cs[lane + 32 * kk], Wr[lane + 32 * kk], s);
#pragma unroll
            for (int o = 16; o; o >>= 1)
                s += __shfl_xor_sync(0xFFFFFFFFu, s, o);
            if (lane == 0) ys[n] = siluf(s + b_out[n]);
        }
    }
    __syncthreads();

    if (t == 0) {
        float g[5];
#pragma unroll
        for (int gi = 0; gi < 5; gi++) {
            float s = 0.0f;
#pragma unroll
            for (int i = 0; i < 5; i++) {
                float yv = ys[gi * 5 + i];
                s = fmaf(yv, yv, s);
            }
            g[gi] = s;
        }
        // quad = m11(q0^2+q1^2) + (m12+m21)(q0q2+q1q3) + m22(q2^2+q3^2)
        const float m11 = g[0], m12 = g[1], m21 = g[2], m22 = g[3], mpp = g[4];
        const float q0 = ys[0], q1 = ys[1], q2 = ys[2], q3 = ys[3];
        float quad = m11 * (q0 * q0 + q1 * q1)
                   + (m12 + m21) * (q0 * q2 + q1 * q3)
                   + m22 * (q2 * q2 + q3 * q3);
        out[b] = quad + mpp;
    }
}

// ---------------------------------------------------------------------------
extern "C" void kernel_launch(void* const* d_in, const int* in_sizes, int n_in,
                              void* d_out, int out_size)
{
    const float* x     = (const float*)d_in[0];
    // d_in[1] = na (int32, always 4) — unused (q = y[:, :4] hardcoded)
    const float* W_in  = (const float*)d_in[2];
    const float* b_in  = (const float*)d_in[3];
    const float* Aq    = (const float*)d_in[4];
    const float* Bq    = (const float*)d_in[5];
    const float* Ak    = (const float*)d_in[6];
    const float* Bk    = (const float*)d_in[7];
    const float* Av    = (const float*)d_in[8];
    const float* Bv    = (const float*)d_in[9];
    const float* W_out = (const float*)d_in[10];
    const float* b_out = (const float*)d_in[11];
    float* out = (float*)d_out;

    float *h, *Qp, *Kp, *Vp;
    cudaGetSymbolAddress((void**)&h,  g_h);
    cudaGetSymbolAddress((void**)&Qp, g_Q);
    cudaGetSymbolAddress((void**)&Kp, g_K);
    cudaGetSymbolAddress((void**)&Vp, g_V);

    // h = silu(x @ W_in^T + b_in)   [512,128] -> [512,512]
    gemm_silu_kernel<<<dim3(8, 8, 1), 64>>>(
        x, W_in, W_in, W_in, b_in, b_in, b_in, h, h, h, H2, IN_DIM);

    // Q,K,V = silu(h @ A*^T + B*) fused via grid.z
    gemm_silu_kernel<<<dim3(8, 8, 3), 64>>>(
        h, Aq, Ak, Av, Bq, Bk, Bv, Qp, Kp, Vp, H2, H2);

    // rank-1 softmax attention + output projection + quad epilogue
    attn_out_kernel<<<BSZ, H2>>>(W_out, b_out, out);
}